// round 12
// baseline (speedup 1.0000x reference)
#include <cuda_runtime.h>
#include <cstdint>

#define BATCH 512
#define TLEN  512
#define S     64
#define NEG_INF -10000.0f
#define RD    8            // backtrace ring depth

typedef unsigned long long ull;

// vmax history: [b][t-1][n], pre-feat step maxima. 512*511*64*4 = 66.98 MB.
__device__ __align__(16) float g_vmax[(size_t)BATCH * (TLEN - 1) * S];

__device__ __forceinline__ ull ADD2(ull a, ull b) {
    ull r; asm("add.rn.f32x2 %0, %1, %2;" : "=l"(r) : "l"(a), "l"(b)); return r;
}
// max of packed halves; mov.b64 split is register aliasing (0 instr).
__device__ __forceinline__ float PMAX(ull v) {
    unsigned int l, h;
    asm("mov.b64 {%0,%1}, %2;" : "=r"(l), "=r"(h) : "l"(v));
    return fmaxf(__uint_as_float(l), __uint_as_float(h));
}

// one warp per block; warp processes TWO independent batches
__global__ __launch_bounds__(32, 1) void viterbi_all(
    const float* __restrict__ logits,       // (B, T, S)
    const float* __restrict__ masks,        // (B, T)
    const float* __restrict__ transitions,  // (S, S) [next, prev]
    float* __restrict__ out)                // [0,B): path_score ; [B,...): best_seq
{
    const int l  = threadIdx.x;            // lane
    const int b0 = blockIdx.x * 2;
    const int b1 = b0 + 1;

    __shared__ __align__(16) float tr_s[S * S];        // 16 KB
    __shared__ __align__(16) float fvb[2][2][S];       // [batch][buf][tag]
    __shared__ __align__(16) float smask[2][TLEN];
    __shared__ __align__(16) float ring_vm[2][RD][S];
    __shared__ __align__(16) float ring_fv[2][RD][S];
    __shared__ unsigned char seq_s[2][TLEN];

    // ---- stage transitions + mask rows ----
    {
        const float4* ts = (const float4*)transitions;
        float4* td = (float4*)tr_s;
#pragma unroll
        for (int i = 0; i < S * S / 4 / 32; i++) td[l + 32 * i] = ts[l + 32 * i];
        const float4* m0 = (const float4*)(masks + (size_t)b0 * TLEN);
        const float4* m1 = (const float4*)(masks + (size_t)b1 * TLEN);
        float4* d0 = (float4*)smask[0];
        float4* d1 = (float4*)smask[1];
#pragma unroll
        for (int i = 0; i < 4; i++) { d0[l + 32 * i] = m0[l + 32 * i];
                                      d1[l + 32 * i] = m1[l + 32 * i]; }
        fvb[0][0][l] = (l == 0) ? 0.0f : NEG_INF;  fvb[0][0][l + 32] = NEG_INF;
        fvb[1][0][l] = (l == 0) ? 0.0f : NEG_INF;  fvb[1][0][l + 32] = NEG_INF;
    }
    __syncwarp();

    // ---- transition rows for tags l and l+32 (shared across both batches) ----
    ull trA[32], trB[32];
    {
        const ulonglong2* ta = (const ulonglong2*)(tr_s + l * S);
        const ulonglong2* tb = (const ulonglong2*)(tr_s + (l + 32) * S);
#pragma unroll
        for (int i = 0; i < 16; i++) {
            ulonglong2 va = ta[i]; trA[2 * i] = va.x; trA[2 * i + 1] = va.y;
            ulonglong2 vb = tb[i]; trB[2 * i] = vb.x; trB[2 * i + 1] = vb.y;
        }
    }

    const float* lg0 = logits + (size_t)b0 * TLEN * S;
    const float* lg1 = logits + (size_t)b1 * TLEN * S;
    float* vm0 = g_vmax + (size_t)b0 * (TLEN - 1) * S;
    float* vm1 = g_vmax + (size_t)b1 * (TLEN - 1) * S;

    // ---- emission prefetch depth 2, both batches, both tags ----
    float pa0[2], pb0[2], pa1[2], pb1[2];
#pragma unroll
    for (int i = 0; i < 2; i++) {
        pa0[i] = lg0[(1 + i) * S + l];  pb0[i] = lg0[(1 + i) * S + l + 32];
        pa1[i] = lg1[(1 + i) * S + l];  pb1[i] = lg1[(1 + i) * S + l + 32];
    }

    // ============ forward: two interleaved independent recursions ============
#pragma unroll 2
    for (int t = 1; t < TLEN; t++) {
        float fA0 = pa0[0], fB0 = pb0[0], fA1 = pa1[0], fB1 = pb1[0];
        pa0[0] = pa0[1]; pb0[0] = pb0[1]; pa1[0] = pa1[1]; pb1[0] = pb1[1];
        int tpi = t + 2; if (tpi > TLEN - 1) tpi = TLEN - 1;
        pa0[1] = lg0[tpi * S + l];  pb0[1] = lg0[tpi * S + l + 32];
        pa1[1] = lg1[tpi * S + l];  pb1[1] = lg1[tpi * S + l + 32];

        float m0 = smask[0][t], m1 = smask[1][t];

        const ulonglong2* f0p = (const ulonglong2*)fvb[0][(t - 1) & 1];
        const ulonglong2* f1p = (const ulonglong2*)fvb[1][(t - 1) & 1];

        float aA0[4], aB0[4], aA1[4], aB1[4];
#pragma unroll
        for (int j = 0; j < 4; j++) {
            int k = 8 * j;
            {   // batch 0, group j
                ulonglong2 q0 = f0p[4 * j], q1 = f0p[4 * j + 1],
                           q2 = f0p[4 * j + 2], q3 = f0p[4 * j + 3];
                float x0 = PMAX(ADD2(q0.x, trA[k + 0])), x1 = PMAX(ADD2(q0.y, trA[k + 1]));
                float x2 = PMAX(ADD2(q1.x, trA[k + 2])), x3 = PMAX(ADD2(q1.y, trA[k + 3]));
                float x4 = PMAX(ADD2(q2.x, trA[k + 4])), x5 = PMAX(ADD2(q2.y, trA[k + 5]));
                float x6 = PMAX(ADD2(q3.x, trA[k + 6])), x7 = PMAX(ADD2(q3.y, trA[k + 7]));
                aA0[j] = fmaxf(fmaxf(fmaxf(x0, x1), fmaxf(x2, x3)),
                               fmaxf(fmaxf(x4, x5), fmaxf(x6, x7)));
                float y0 = PMAX(ADD2(q0.x, trB[k + 0])), y1 = PMAX(ADD2(q0.y, trB[k + 1]));
                float y2 = PMAX(ADD2(q1.x, trB[k + 2])), y3 = PMAX(ADD2(q1.y, trB[k + 3]));
                float y4 = PMAX(ADD2(q2.x, trB[k + 4])), y5 = PMAX(ADD2(q2.y, trB[k + 5]));
                float y6 = PMAX(ADD2(q3.x, trB[k + 6])), y7 = PMAX(ADD2(q3.y, trB[k + 7]));
                aB0[j] = fmaxf(fmaxf(fmaxf(y0, y1), fmaxf(y2, y3)),
                               fmaxf(fmaxf(y4, y5), fmaxf(y6, y7)));
            }
            {   // batch 1, group j
                ulonglong2 q0 = f1p[4 * j], q1 = f1p[4 * j + 1],
                           q2 = f1p[4 * j + 2], q3 = f1p[4 * j + 3];
                float x0 = PMAX(ADD2(q0.x, trA[k + 0])), x1 = PMAX(ADD2(q0.y, trA[k + 1]));
                float x2 = PMAX(ADD2(q1.x, trA[k + 2])), x3 = PMAX(ADD2(q1.y, trA[k + 3]));
                float x4 = PMAX(ADD2(q2.x, trA[k + 4])), x5 = PMAX(ADD2(q2.y, trA[k + 5]));
                float x6 = PMAX(ADD2(q3.x, trA[k + 6])), x7 = PMAX(ADD2(q3.y, trA[k + 7]));
                aA1[j] = fmaxf(fmaxf(fmaxf(x0, x1), fmaxf(x2, x3)),
                               fmaxf(fmaxf(x4, x5), fmaxf(x6, x7)));
                float y0 = PMAX(ADD2(q0.x, trB[k + 0])), y1 = PMAX(ADD2(q0.y, trB[k + 1]));
                float y2 = PMAX(ADD2(q1.x, trB[k + 2])), y3 = PMAX(ADD2(q1.y, trB[k + 3]));
                float y4 = PMAX(ADD2(q2.x, trB[k + 4])), y5 = PMAX(ADD2(q2.y, trB[k + 5]));
                float y6 = PMAX(ADD2(q3.x, trB[k + 6])), y7 = PMAX(ADD2(q3.y, trB[k + 7]));
                aB1[j] = fmaxf(fmaxf(fmaxf(y0, y1), fmaxf(y2, y3)),
                               fmaxf(fmaxf(y4, y5), fmaxf(y6, y7)));
            }
        }
        float vA0 = fmaxf(fmaxf(aA0[0], aA0[1]), fmaxf(aA0[2], aA0[3]));
        float vB0 = fmaxf(fmaxf(aB0[0], aB0[1]), fmaxf(aB0[2], aB0[3]));
        float vA1 = fmaxf(fmaxf(aA1[0], aA1[1]), fmaxf(aA1[2], aA1[3]));
        float vB1 = fmaxf(fmaxf(aB1[0], aB1[1]), fmaxf(aB1[2], aB1[3]));

        const int r = t - 1;
        vm0[r * S + l]      = vA0;   // fire-and-forget STG
        vm0[r * S + l + 32] = vB0;
        vm1[r * S + l]      = vA1;
        vm1[r * S + l + 32] = vB1;
        fvb[0][t & 1][l]      = __fadd_rn(vA0, __fmul_rn(fA0, m0));
        fvb[0][t & 1][l + 32] = __fadd_rn(vB0, __fmul_rn(fB0, m0));
        fvb[1][t & 1][l]      = __fadd_rn(vA1, __fmul_rn(fA1, m1));
        fvb[1][t & 1][l + 32] = __fadd_rn(vB1, __fmul_rn(fB1, m1));
        __syncwarp();
        if (t == TLEN - 1 && l == 31) {          // path_score quirk (tag 63)
            out[b0] = vB0;
            out[b1] = vB1;
        }
    }

    // ============ backtrace: both batches interleaved in one warp ============
    {
        auto pref = [&](int bb, const float* lgx, const float* vmx, int i) {
            int sl = i & (RD - 1);
            float2 fv;
            if (i == 0) {
                fv.x = (2 * l == 0) ? 0.0f : NEG_INF;
                fv.y = NEG_INF;
            } else {
                float2 vp = *(const float2*)(vmx + (size_t)(i - 1) * S + 2 * l);
                float2 ft = *(const float2*)(lgx + (size_t)i * S + 2 * l);
                float mm = smask[bb][i];
                fv.x = __fadd_rn(vp.x, __fmul_rn(ft.x, mm));
                fv.y = __fadd_rn(vp.y, __fmul_rn(ft.y, mm));
            }
            *(float2*)&ring_fv[bb][sl][2 * l] = fv;
            float2 vm = *(const float2*)(vmx + (size_t)i * S + 2 * l);
            *(float2*)&ring_vm[bb][sl][2 * l] = vm;
        };

        for (int j = 0; j < RD - 1; j++) {
            int i = (TLEN - 2) - j;
            if (i >= 0) { pref(0, lg0, vm0, i); pref(1, lg1, vm1, i); }
        }
        __syncwarp();

        float2 fc0 = *(const float2*)&ring_fv[0][(TLEN - 2) & (RD - 1)][2 * l];
        float2 fc1 = *(const float2*)&ring_fv[1][(TLEN - 2) & (RD - 1)][2 * l];

        // lowest p with fv[p] + tr[tag][p] == vmax_hist[i][tag]
        auto eq_step = [&](int bb, float2 fc, int i, int tag) -> int {
            float tgt = ring_vm[bb][i & (RD - 1)][tag];
            float2 trp = *(const float2*)(tr_s + tag * S + 2 * l);
            float c0 = __fadd_rn(fc.x, trp.x);
            float c1 = __fadd_rn(fc.y, trp.y);
            unsigned m0 = __ballot_sync(0xffffffffu, c0 == tgt);
            unsigned m1 = __ballot_sync(0xffffffffu, c1 == tgt);
            int p0 = m0 ? ((__ffs(m0) - 1) << 1) : 1000;
            int p1 = m1 ? (((__ffs(m1) - 1) << 1) + 1) : 1000;
            int p = p0 < p1 ? p0 : p1;
            return p & 63;
        };

        // torch quirk: seed from bp(T-2, S-1); last table applied twice
        int tag0 = eq_step(0, fc0, TLEN - 2, S - 1);
        int tag1 = eq_step(1, fc1, TLEN - 2, S - 1);
        for (int i = TLEN - 2; i >= 0; i--) {
            if (l == 0) { seq_s[0][i] = (unsigned char)tag0;
                          seq_s[1][i] = (unsigned char)tag1; }
            int nt0 = eq_step(0, fc0, i, tag0);
            int nt1 = eq_step(1, fc1, i, tag1);
            int ip = i - (RD - 1);
            if (ip >= 0) { pref(0, lg0, vm0, ip); pref(1, lg1, vm1, ip); }
            __syncwarp();
            if (i > 0) {
                fc0 = *(const float2*)&ring_fv[0][(i - 1) & (RD - 1)][2 * l];
                fc1 = *(const float2*)&ring_fv[1][(i - 1) & (RD - 1)][2 * l];
            }
            tag0 = nt0; tag1 = nt1;
        }
    }
    __syncwarp();

    // ---- coalesced output of both sequences ----
    float* o0 = out + BATCH + (size_t)b0 * (TLEN - 1);
    float* o1 = out + BATCH + (size_t)b1 * (TLEN - 1);
    for (int i = l; i < TLEN - 1; i += 32) {
        o0[i] = (float)seq_s[0][i];
        o1[i] = (float)seq_s[1][i];
    }
}

extern "C" void kernel_launch(void* const* d_in, const int* in_sizes, int n_in,
                              void* d_out, int out_size)
{
    const float* logits      = (const float*)d_in[0];
    const float* masks       = (const float*)d_in[1];
    const float* transitions = (const float*)d_in[2];
    float* out = (float*)d_out;

    viterbi_all<<<BATCH / 2, 32>>>(logits, masks, transitions, out);
}

// round 13
// speedup vs baseline: 1.9858x; 1.9858x over previous
#include <cuda_runtime.h>
#include <cstdint>

#define BATCH 512
#define TLEN  512
#define S     64
#define NEG_INF -10000.0f
#define NTHR  128   // tid = 2*n + h ; n = next-tag, h = prev-half

typedef unsigned long long ull;

__device__ __forceinline__ ull ADD2(ull a, ull b) {
    ull r; asm("add.rn.f32x2 %0, %1, %2;" : "=l"(r) : "l"(a), "l"(b)); return r;
}
// mov.b64 pair split is register aliasing (0 instr).
__device__ __forceinline__ void UNPK(ull v, float& lo, float& hi) {
    unsigned int l, h;
    asm("mov.b64 {%0,%1}, %2;" : "=r"(l), "=r"(h) : "l"(v));
    lo = __uint_as_float(l); hi = __uint_as_float(h);
}

__global__ __launch_bounds__(NTHR) void viterbi_all(
    const float* __restrict__ logits,       // (B, T, S)
    const float* __restrict__ masks,        // (B, T)
    const float* __restrict__ transitions,  // (S, S) [next, prev]
    float* __restrict__ out)                // [0,B): path_score ; [B,...): best_seq
{
    const int b   = blockIdx.x;
    const int tid = threadIdx.x;
    const int n   = tid >> 1;     // next tag 0..63
    const int h   = tid & 1;      // prev half 0..1

    __shared__ __align__(16) float fvbuf[2][S];
    __shared__ __align__(16) float smask[TLEN];
    __shared__ __align__(16) unsigned char bp_s[(TLEN - 1) * S]; // 32704 B
    __shared__ unsigned char seq_s[TLEN];

    // ---- my 32 transitions (row n, half h) as 16 packed f32x2 (from L2) ----
    ull tr2[16];
    {
        const ulonglong2* tp =
            (const ulonglong2*)(transitions + n * S + h * 32);
#pragma unroll
        for (int i = 0; i < 8; i++) {
            ulonglong2 v = tp[i];
            tr2[2 * i] = v.x; tr2[2 * i + 1] = v.y;
        }
    }

    // ---- stage mask row (2 KB); init fv ----
    {
        const float4* ms = (const float4*)(masks + (size_t)b * TLEN);
        ((float4*)smask)[tid] = ms[tid];
        if (h == 0) fvbuf[0][n] = (n == 0) ? 0.0f : NEG_INF;
    }
    __syncthreads();

    const float* lg = logits + (size_t)b * TLEN * S;

    // ---- emission prefetch pipeline (depth 4) ----
    float fb[4];
#pragma unroll
    for (int i = 0; i < 4; i++) fb[i] = lg[(1 + i) * S + n];

    // =================== forward: tournament argmax ===================
#pragma unroll 4
    for (int t = 1; t < TLEN; t++) {
        float feat = fb[0];
        fb[0] = fb[1]; fb[1] = fb[2]; fb[2] = fb[3];
        int tpi = t + 4; if (tpi > TLEN - 1) tpi = TLEN - 1;
        fb[3] = lg[tpi * S + n];

        float m = smask[t];

        const ulonglong2* fvp =
            (const ulonglong2*)(&fvbuf[(t - 1) & 1][32 * h]);

        // level 0: 16 packed adds -> 16 (value, index) pairs
        float v16[16]; int i16[16];
#pragma unroll
        for (int k = 0; k < 8; k++) {
            ulonglong2 F = fvp[k];          // fv[32h+4k .. 32h+4k+3]
            float lo0, hi0, lo1, hi1;
            UNPK(ADD2(F.x, tr2[2 * k]),     lo0, hi0);
            UNPK(ADD2(F.y, tr2[2 * k + 1]), lo1, hi1);
            const int p0 = 32 * h + 4 * k;
            v16[2 * k]     = fmaxf(lo0, hi0);
            i16[2 * k]     = (hi0 > lo0) ? p0 + 1 : p0;      // tie -> lower p
            v16[2 * k + 1] = fmaxf(lo1, hi1);
            i16[2 * k + 1] = (hi1 > lo1) ? p0 + 3 : p0 + 2;
        }
        // balanced tournament; 'a' side is always lower p, strict > keeps a on tie
        float v8[8]; int i8[8];
#pragma unroll
        for (int k = 0; k < 8; k++) {
            bool g = v16[2 * k + 1] > v16[2 * k];
            v8[k] = fmaxf(v16[2 * k], v16[2 * k + 1]);
            i8[k] = g ? i16[2 * k + 1] : i16[2 * k];
        }
        float v4[4]; int i4[4];
#pragma unroll
        for (int k = 0; k < 4; k++) {
            bool g = v8[2 * k + 1] > v8[2 * k];
            v4[k] = fmaxf(v8[2 * k], v8[2 * k + 1]);
            i4[k] = g ? i8[2 * k + 1] : i8[2 * k];
        }
        float v2[2]; int i2[2];
#pragma unroll
        for (int k = 0; k < 2; k++) {
            bool g = v4[2 * k + 1] > v4[2 * k];
            v2[k] = fmaxf(v4[2 * k], v4[2 * k + 1]);
            i2[k] = g ? i4[2 * k + 1] : i4[2 * k];
        }
        bool gf = v2[1] > v2[0];
        float v = fmaxf(v2[0], v2[1]);
        int idx = gf ? i2[1] : i2[0];

        // merge the two prev halves: h=0 owns lower p range; strict > keeps it on tie
        float vo = __shfl_xor_sync(0xffffffffu, v, 1);
        int   io = __shfl_xor_sync(0xffffffffu, idx, 1);
        if (h == 0) {
            if (vo > v) { v = vo; idx = io; }
            bp_s[(t - 1) * S + n] = (unsigned char)idx;
            // torch quirk: path_score = pre-feat vmax at n = S-1, last step
            if (t == TLEN - 1 && n == S - 1) out[b] = v;
            fvbuf[t & 1][n] = __fadd_rn(v, __fmul_rn(feat, m));
        }
        __syncthreads();
    }

    // ---- backtrace walk in shared (single thread, LDS chain) ----
    if (tid == 0) {
        int tag = bp_s[(TLEN - 2) * S + (S - 1)];   // seed (torch quirk)
        for (int i = TLEN - 2; i >= 0; i--) {
            seq_s[i] = (unsigned char)tag;
            tag = bp_s[i * S + tag];
        }
    }
    __syncthreads();

    // ---- coalesced output ----
    float* o = out + BATCH + (size_t)b * (TLEN - 1);
    for (int i = tid; i < TLEN - 1; i += NTHR) o[i] = (float)seq_s[i];
}

extern "C" void kernel_launch(void* const* d_in, const int* in_sizes, int n_in,
                              void* d_out, int out_size)
{
    const float* logits      = (const float*)d_in[0];
    const float* masks       = (const float*)d_in[1];
    const float* transitions = (const float*)d_in[2];
    float* out = (float*)d_out;

    viterbi_all<<<BATCH, NTHR>>>(logits, masks, transitions, out);
}